// round 1
// baseline (speedup 1.0000x reference)
#include <cuda_runtime.h>
#include <math.h>

#define N_NODES 4096
#define M_NODES 8192
#define DIM 128
#define NUM_ITERS 3

// Scratch (device globals; no allocations allowed)
__device__ float g_Xu[M_NODES * DIM];
__device__ float g_Y[M_NODES * DIM];
__device__ float g_dinv[M_NODES];

// ---------------------------------------------------------------------------
// Generic tiled GEMM with epilogue:
//   C[i,j] = epi( sum_k A[i,k]*B[k,j] )
//   epi(v) = maybe_relu( v*rs[i] + rb[i] + cb[j] )
// Tiles: 64x64 output, BK=32, 256 threads, 4x4 micro-tile.
// ---------------------------------------------------------------------------
#define BM 64
#define BN 64
#define BK 32

__global__ __launch_bounds__(256) void gemm_ep(
    const float* __restrict__ A, const float* __restrict__ B, float* __restrict__ C,
    int K, int lda, int ldb, int ldc,
    const float* __restrict__ rs, const float* __restrict__ rb,
    const float* __restrict__ cb, int do_relu)
{
    __shared__ float As[BK][BM + 1];   // A tile, transposed (k-major)
    __shared__ float Bs[BK][BN];

    const int tid = threadIdx.x;
    const int tx = tid & 15;          // 16 col groups
    const int ty = tid >> 4;          // 16 row groups
    const int row0 = blockIdx.y * BM;
    const int col0 = blockIdx.x * BN;

    float acc[4][4];
#pragma unroll
    for (int i = 0; i < 4; i++)
#pragma unroll
        for (int j = 0; j < 4; j++) acc[i][j] = 0.0f;

    for (int k0 = 0; k0 < K; k0 += BK) {
        // Stage A tile (BM x BK) transposed into As
#pragma unroll
        for (int l = 0; l < 2; l++) {
            int idx = tid + l * 256;          // 0..511
            int r = idx >> 3;                 // row in tile
            int kg = (idx & 7) << 2;          // k group *4
            float4 v = *reinterpret_cast<const float4*>(
                A + (size_t)(row0 + r) * lda + k0 + kg);
            As[kg + 0][r] = v.x;
            As[kg + 1][r] = v.y;
            As[kg + 2][r] = v.z;
            As[kg + 3][r] = v.w;
        }
        // Stage B tile (BK x BN)
#pragma unroll
        for (int l = 0; l < 2; l++) {
            int idx = tid + l * 256;
            int r = idx >> 4;
            int cg = (idx & 15) << 2;
            *reinterpret_cast<float4*>(&Bs[r][cg]) =
                *reinterpret_cast<const float4*>(B + (size_t)(k0 + r) * ldb + col0 + cg);
        }
        __syncthreads();

#pragma unroll
        for (int kk = 0; kk < BK; kk++) {
            float a0 = As[kk][ty * 4 + 0];
            float a1 = As[kk][ty * 4 + 1];
            float a2 = As[kk][ty * 4 + 2];
            float a3 = As[kk][ty * 4 + 3];
            float4 bv = *reinterpret_cast<const float4*>(&Bs[kk][tx * 4]);
            acc[0][0] = fmaf(a0, bv.x, acc[0][0]);
            acc[0][1] = fmaf(a0, bv.y, acc[0][1]);
            acc[0][2] = fmaf(a0, bv.z, acc[0][2]);
            acc[0][3] = fmaf(a0, bv.w, acc[0][3]);
            acc[1][0] = fmaf(a1, bv.x, acc[1][0]);
            acc[1][1] = fmaf(a1, bv.y, acc[1][1]);
            acc[1][2] = fmaf(a1, bv.z, acc[1][2]);
            acc[1][3] = fmaf(a1, bv.w, acc[1][3]);
            acc[2][0] = fmaf(a2, bv.x, acc[2][0]);
            acc[2][1] = fmaf(a2, bv.y, acc[2][1]);
            acc[2][2] = fmaf(a2, bv.z, acc[2][2]);
            acc[2][3] = fmaf(a2, bv.w, acc[2][3]);
            acc[3][0] = fmaf(a3, bv.x, acc[3][0]);
            acc[3][1] = fmaf(a3, bv.y, acc[3][1]);
            acc[3][2] = fmaf(a3, bv.z, acc[3][2]);
            acc[3][3] = fmaf(a3, bv.w, acc[3][3]);
        }
        __syncthreads();
    }

#pragma unroll
    for (int ii = 0; ii < 4; ii++) {
        int i = row0 + ty * 4 + ii;
        float s = rs ? rs[i] : 1.0f;
        float rbv = rb ? rb[i] : 0.0f;
        float4 out;
        float* o = &out.x;
#pragma unroll
        for (int jj = 0; jj < 4; jj++) {
            int j = col0 + tx * 4 + jj;
            float v = acc[ii][jj] * s + rbv + (cb ? cb[j] : 0.0f);
            if (do_relu) v = fmaxf(v, 0.0f);
            o[jj] = v;
        }
        *reinterpret_cast<float4*>(C + (size_t)i * ldc + col0 + tx * 4) = out;
    }
}

// ---------------------------------------------------------------------------
// Symmetric P = sigmoid(U @ U^T) over upper-triangular 64x64 tile pairs,
// mirroring each off-diagonal tile. U is [n, 128] row-major.
// Writes into P with row/col offset `off`, leading dim ldp.
// ---------------------------------------------------------------------------
__global__ __launch_bounds__(256) void xxt_sigmoid(
    const float* __restrict__ U, int n, float* __restrict__ P, int ldp, int off)
{
    __shared__ float It[BK][BM + 1];
    __shared__ float Jt[BK][BM + 1];

    int b = blockIdx.x;
    // map linear pair index -> (bi <= bj)
    int bj = (int)((sqrtf(8.0f * (float)b + 1.0f) - 1.0f) * 0.5f);
    while ((bj + 1) * (bj + 2) / 2 <= b) bj++;
    while (bj * (bj + 1) / 2 > b) bj--;
    int bi = b - bj * (bj + 1) / 2;

    const int tid = threadIdx.x;
    const int tx = tid & 15;
    const int ty = tid >> 4;

    float acc[4][4];
#pragma unroll
    for (int i = 0; i < 4; i++)
#pragma unroll
        for (int j = 0; j < 4; j++) acc[i][j] = 0.0f;

    for (int k0 = 0; k0 < DIM; k0 += BK) {
#pragma unroll
        for (int l = 0; l < 2; l++) {
            int idx = tid + l * 256;
            int r = idx >> 3;
            int kg = (idx & 7) << 2;
            float4 v = *reinterpret_cast<const float4*>(
                U + (size_t)(bi * 64 + r) * DIM + k0 + kg);
            It[kg + 0][r] = v.x;
            It[kg + 1][r] = v.y;
            It[kg + 2][r] = v.z;
            It[kg + 3][r] = v.w;
            float4 w = *reinterpret_cast<const float4*>(
                U + (size_t)(bj * 64 + r) * DIM + k0 + kg);
            Jt[kg + 0][r] = w.x;
            Jt[kg + 1][r] = w.y;
            Jt[kg + 2][r] = w.z;
            Jt[kg + 3][r] = w.w;
        }
        __syncthreads();
#pragma unroll
        for (int kk = 0; kk < BK; kk++) {
            float a0 = It[kk][ty * 4 + 0];
            float a1 = It[kk][ty * 4 + 1];
            float a2 = It[kk][ty * 4 + 2];
            float a3 = It[kk][ty * 4 + 3];
            float b0 = Jt[kk][tx * 4 + 0];
            float b1 = Jt[kk][tx * 4 + 1];
            float b2 = Jt[kk][tx * 4 + 2];
            float b3 = Jt[kk][tx * 4 + 3];
            acc[0][0] = fmaf(a0, b0, acc[0][0]);
            acc[0][1] = fmaf(a0, b1, acc[0][1]);
            acc[0][2] = fmaf(a0, b2, acc[0][2]);
            acc[0][3] = fmaf(a0, b3, acc[0][3]);
            acc[1][0] = fmaf(a1, b0, acc[1][0]);
            acc[1][1] = fmaf(a1, b1, acc[1][1]);
            acc[1][2] = fmaf(a1, b2, acc[1][2]);
            acc[1][3] = fmaf(a1, b3, acc[1][3]);
            acc[2][0] = fmaf(a2, b0, acc[2][0]);
            acc[2][1] = fmaf(a2, b1, acc[2][1]);
            acc[2][2] = fmaf(a2, b2, acc[2][2]);
            acc[2][3] = fmaf(a2, b3, acc[2][3]);
            acc[3][0] = fmaf(a3, b0, acc[3][0]);
            acc[3][1] = fmaf(a3, b1, acc[3][1]);
            acc[3][2] = fmaf(a3, b2, acc[3][2]);
            acc[3][3] = fmaf(a3, b3, acc[3][3]);
        }
        __syncthreads();
    }

    float sv[4][4];
#pragma unroll
    for (int ii = 0; ii < 4; ii++)
#pragma unroll
        for (int jj = 0; jj < 4; jj++)
            sv[ii][jj] = 1.0f / (1.0f + expf(-acc[ii][jj]));

    const int gi0 = off + bi * 64 + ty * 4;
    const int gj0 = off + bj * 64 + tx * 4;
#pragma unroll
    for (int ii = 0; ii < 4; ii++) {
        float4 out = make_float4(sv[ii][0], sv[ii][1], sv[ii][2], sv[ii][3]);
        *reinterpret_cast<float4*>(P + (size_t)(gi0 + ii) * ldp + gj0) = out;
    }
    if (bi != bj) {
#pragma unroll
        for (int jj = 0; jj < 4; jj++) {
            float4 out = make_float4(sv[0][jj], sv[1][jj], sv[2][jj], sv[3][jj]);
            *reinterpret_cast<float4*>(P + (size_t)(gj0 + jj) * ldp + gi0) = out;
        }
    }
}

// ---------------------------------------------------------------------------
// dinv[i] = rsqrt(sum_j P[i,j])  (P is symmetric: row sum == column sum)
// ---------------------------------------------------------------------------
__global__ __launch_bounds__(256) void deg_kernel(
    const float* __restrict__ P, float* __restrict__ dinv, int m)
{
    __shared__ float red[256];
    const int row = blockIdx.x;
    const float4* p = reinterpret_cast<const float4*>(P + (size_t)row * m);
    float s = 0.0f;
    for (int j = threadIdx.x; j < (m >> 2); j += 256) {
        float4 v = p[j];
        s += (v.x + v.y) + (v.z + v.w);
    }
    red[threadIdx.x] = s;
    __syncthreads();
    for (int st = 128; st > 0; st >>= 1) {
        if (threadIdx.x < st) red[threadIdx.x] += red[threadIdx.x + st];
        __syncthreads();
    }
    if (threadIdx.x == 0) {
        float d = red[0];
        dinv[row] = d > 0.0f ? rsqrtf(d) : 0.0f;
    }
}

// ---------------------------------------------------------------------------
// Initial block adjacency: P[:N,:N] = A, P[:N,N:] = A^T (== A, bitwise
// symmetric since A = 0.5*(R+R^T)), P[N:,:N] = A. Bottom-right filled by xxt.
// ---------------------------------------------------------------------------
__global__ __launch_bounds__(256) void build_blocks(
    const float* __restrict__ A, float* __restrict__ P)
{
    const int total = N_NODES * (N_NODES / 4);
    int idx = blockIdx.x * 256 + threadIdx.x;
    if (idx >= total) return;
    int i = idx / (N_NODES / 4);
    int j4 = idx % (N_NODES / 4);
    float4 v = reinterpret_cast<const float4*>(A)[(size_t)i * (N_NODES / 4) + j4];
    reinterpret_cast<float4*>(P + (size_t)i * M_NODES)[j4] = v;
    reinterpret_cast<float4*>(P + (size_t)i * M_NODES + N_NODES)[j4] = v;
    reinterpret_cast<float4*>(P + (size_t)(i + N_NODES) * M_NODES)[j4] = v;
}

// ---------------------------------------------------------------------------

extern "C" void kernel_launch(void* const* d_in, const int* in_sizes, int n_in,
                              void* d_out, int out_size)
{
    const float* X   = (const float*)d_in[0];
    const float* A   = (const float*)d_in[1];
    const float* Wup = (const float*)d_in[2];
    const float* bup = (const float*)d_in[3];
    const float* W1  = (const float*)d_in[4];
    const float* b1  = (const float*)d_in[5];
    const float* W2  = (const float*)d_in[6];
    const float* b2  = (const float*)d_in[7];
    float* P = (float*)d_out;   // Adj lives in d_out the whole time

    float *Xu, *Y, *dinv;
    cudaGetSymbolAddress((void**)&Xu, g_Xu);
    cudaGetSymbolAddress((void**)&Y, g_Y);
    cudaGetSymbolAddress((void**)&dinv, g_dinv);

    // Xu[0:N] = X
    cudaMemcpyAsync(Xu, X, (size_t)N_NODES * DIM * sizeof(float),
                    cudaMemcpyDeviceToDevice);

    // Xu[N:M] = new_nodes = W_up @ X + b_up
    {
        dim3 g(DIM / BN, N_NODES / BM);
        gemm_ep<<<g, 256>>>(Wup, X, Xu + (size_t)N_NODES * DIM,
                            N_NODES, N_NODES, DIM, DIM,
                            nullptr, bup, nullptr, 0);
    }

    // Block adjacency into P
    build_blocks<<<(N_NODES * (N_NODES / 4) + 255) / 256, 256>>>(A, P);
    {
        int T = N_NODES / 64;
        xxt_sigmoid<<<T * (T + 1) / 2, 256>>>(Xu + (size_t)N_NODES * DIM,
                                              N_NODES, P, M_NODES, N_NODES);
    }

    dim3 gbig(DIM / BN, M_NODES / BM);   // 2 x 128 = 256 blocks
    for (int it = 0; it < NUM_ITERS; it++) {
        // conv1
        deg_kernel<<<M_NODES, 256>>>(P, dinv, M_NODES);
        gemm_ep<<<gbig, 256>>>(Xu, W1, Y, DIM, DIM, DIM, DIM,
                               dinv, nullptr, nullptr, 0);        // Y = dinv .* (Xu@W1)
        gemm_ep<<<gbig, 256>>>(P, Y, Xu, M_NODES, M_NODES, DIM, DIM,
                               dinv, nullptr, b1, 1);             // Xu = relu(dinv.*(P@Y)+b1)
        // Adj = sigmoid(Xu Xu^T)
        {
            int T = M_NODES / 64;
            xxt_sigmoid<<<T * (T + 1) / 2, 256>>>(Xu, M_NODES, P, M_NODES, 0);
        }
        // conv2
        deg_kernel<<<M_NODES, 256>>>(P, dinv, M_NODES);
        gemm_ep<<<gbig, 256>>>(Xu, W2, Y, DIM, DIM, DIM, DIM,
                               dinv, nullptr, nullptr, 0);
        gemm_ep<<<gbig, 256>>>(P, Y, Xu, M_NODES, M_NODES, DIM, DIM,
                               dinv, nullptr, b2, 1);
        // A_out of iters 0,1 is dead (loop uses the mid-loop Adj) — skip it.
    }

    // Final A_out = sigmoid(Xu Xu^T) written straight into d_out
    {
        int T = M_NODES / 64;
        xxt_sigmoid<<<T * (T + 1) / 2, 256>>>(Xu, M_NODES, P, M_NODES, 0);
    }
    (void)in_sizes; (void)n_in; (void)out_size;
}